// round 7
// baseline (speedup 1.0000x reference)
#include <cuda_runtime.h>

#define NTHR   512
#define KKB    288
#define EPS    1e-6f
#define LAM    1e-3f
#define LN2PI  1.8378770664093453f

// ---- shared-memory float offsets ----
// Union region: cp.async weight stage (2 x 8192 floats) OVERLAPS the two
// per-group reduction buffers (8481 floats each) — time-separated by syncs.
#define SM_UNION   0
#define SM_STAGE0  0            // chunk buffer 0: 8192 floats
#define SM_STAGE1  8192         // chunk buffer 1: 8192 floats
#define SM_REDG0   0            // red group 0: 33*257 = 8481
#define SM_REDG1   8482         // red group 1: ends 16963
#define SM_UNSZ    16964
#define SM_POSE0   (SM_UNSZ)            // 16964, 9216 floats (dup-packed)
#define SM_POSE1   (SM_POSE0 + 9216)    // 26180
#define SM_ACT0    (SM_POSE1 + 9216)    // 35396, 288
#define SM_ACT1    (SM_ACT0 + KKB)      // 35684
#define SM_NMU0    (SM_ACT1 + KKB)      // 35972, 32*18
#define SM_NMU1    (SM_NMU0 + 576)      // 36548
#define SM_IS0     (SM_NMU1 + 576)      // 37124
#define SM_IS1     (SM_IS0 + 576)       // 37700
#define SM_AOUT0   (SM_IS1 + 576)       // 38276
#define SM_AOUT1   (SM_AOUT0 + 32)
#define SM_CC0     (SM_AOUT1 + 32)      // 38340
#define SM_CC1     (SM_CC0 + 32)
#define SM_TOTAL   (SM_CC1 + 32)        // 38404 floats = 153616 bytes

// transposed weights: float4 index = n*128 + q*32 + c
__device__ float4 g_wt[36864];

__global__ void transpose_w_kernel(const float* __restrict__ w) {
    int j = blockIdx.x * 256 + threadIdx.x;
    if (j < 147456) {
        int n = j >> 9, r = j & 511;
        int q = r >> 7, c = (r >> 2) & 31, e = r & 3;
        ((float*)g_wt)[j] = w[n * 512 + c * 16 + q * 4 + e];
    }
}

// ---------- packed f32x2 primitives ----------
typedef unsigned long long u64;

__device__ __forceinline__ u64 fma2(u64 a, u64 b, u64 c) {
    u64 d; asm("fma.rn.f32x2 %0, %1, %2, %3;" : "=l"(d) : "l"(a), "l"(b), "l"(c));
    return d;
}
__device__ __forceinline__ u64 mul2(u64 a, u64 b) {
    u64 d; asm("mul.rn.f32x2 %0, %1, %2;" : "=l"(d) : "l"(a), "l"(b));
    return d;
}
__device__ __forceinline__ u64 add2(u64 a, u64 b) {
    u64 d; asm("add.rn.f32x2 %0, %1, %2;" : "=l"(d) : "l"(a), "l"(b));
    return d;
}
__device__ __forceinline__ u64 pack2(float lo, float hi) {
    u64 r; asm("mov.b64 %0, {%1, %2};" : "=l"(r) : "f"(lo), "f"(hi)); return r;
}
__device__ __forceinline__ float2 unpack2(u64 v) {
    float2 r; asm("mov.b64 {%0, %1}, %2;" : "=f"(r.x), "=f"(r.y) : "l"(v)); return r;
}

// warp max of a float via integer redux (order-preserving u32 mapping)
__device__ __forceinline__ float redmax32f(float v) {
    int i = __float_as_int(v);
    unsigned u = (unsigned)(i ^ ((i >> 31) | 0x80000000));
    unsigned m;
    asm("redux.sync.max.u32 %0, %1, 0xffffffff;" : "=r"(m) : "r"(u));
    int mi = (int)(m ^ ((~(int)m >> 31) | 0x80000000));
    return __int_as_float(mi);
}
__device__ __forceinline__ void wsum32x2(float& a, float& b) {
    #pragma unroll
    for (int d = 16; d; d >>= 1) {
        a += __shfl_xor_sync(0xffffffffu, a, d);
        b += __shfl_xor_sync(0xffffffffu, b, d);
    }
}

// ---------- cp.async staging ----------
__device__ __forceinline__ void issue_chunk(float* sm, int j, int tid) {
    unsigned dst = (unsigned)__cvta_generic_to_shared(
        sm + ((j & 1) ? SM_STAGE1 : SM_STAGE0));
    const float4* src = g_wt + j * 2048;
    #pragma unroll
    for (int i = 0; i < 4; ++i) {
        unsigned d = dst + (unsigned)(tid + i * 512) * 16u;
        const float4* s = src + tid + i * 512;
        asm volatile("cp.async.cg.shared.global [%0], [%1], 16;\n"
                     :: "r"(d), "l"(s) : "memory");
    }
    asm volatile("cp.async.commit_group;\n" ::: "memory");
}
__device__ __forceinline__ void cp_wait1() {
    asm volatile("cp.async.wait_group 1;\n" ::: "memory");
}
__device__ __forceinline__ void cp_wait0() {
    asm volatile("cp.async.wait_group 0;\n" ::: "memory");
}

// compute v from SMEM-staged weights + SMEM dup-packed pose (broadcast)
__device__ __forceinline__ void compute_v2s(const ulonglong2* __restrict__ Wp,
                                            const float* __restrict__ poserow,
                                            u64* __restrict__ v2) {
    ulonglong2 w0 = Wp[0], w1 = Wp[32], w2 = Wp[64], w3 = Wp[96];
    const ulonglong2* __restrict__ P = (const ulonglong2*)poserow;
    #pragma unroll
    for (int i = 0; i < 4; ++i) {
        ulonglong2 pa = P[2 * i];
        ulonglong2 pb = P[2 * i + 1];
        v2[2*i]   = fma2(pa.x, w0.x, fma2(pa.y, w1.x, fma2(pb.x, w2.x, mul2(pb.y, w3.x))));
        v2[2*i+1] = fma2(pa.x, w0.y, fma2(pa.y, w1.y, fma2(pb.x, w2.y, mul2(pb.y, w3.y))));
    }
}

__device__ __forceinline__ float dist16(const u64* __restrict__ v2,
                                        const u64* __restrict__ nmu2,
                                        const u64* __restrict__ is2) {
    u64 acc = 0ull;
    #pragma unroll
    for (int pp = 0; pp < 8; ++pp) {
        u64 d = add2(v2[pp], nmu2[pp]);
        acc = fma2(d, mul2(d, is2[pp]), acc);
    }
    float2 df = unpack2(acc);
    return df.x + df.y;
}

__device__ __forceinline__ void macc2(float r, const u64* __restrict__ v2,
                                      u64* __restrict__ S1, u64* __restrict__ S2) {
    u64 r2 = pack2(r, r);
    #pragma unroll
    for (int pp = 0; pp < 8; ++pp) {
        u64 rv = mul2(r2, v2[pp]);
        S1[pp] = add2(S1[pp], rv);
        S2[pp] = fma2(rv, v2[pp], S2[pp]);
    }
}

__device__ __forceinline__ void store_red(float* __restrict__ redb, int warp8, int c,
                                          const u64* __restrict__ S1,
                                          const u64* __restrict__ S2, float rs) {
    float* base = redb + warp8 * 32 + c;
    #pragma unroll
    for (int pp = 0; pp < 8; ++pp) {
        float2 a = unpack2(S1[pp]);
        float2 b = unpack2(S2[pp]);
        base[(2*pp)    * 257] = a.x;
        base[(2*pp+1)  * 257] = a.y;
        base[(2*pp+16) * 257] = b.x;
        base[(2*pp+17) * 257] = b.y;
    }
    base[32 * 257] = rs;
}

// parallel finalize within a 256-thread position group
__device__ __forceinline__ void finalize(float* __restrict__ sm, const float* __restrict__ redb,
                                         int grp_base_nmu, int grp_base_is,
                                         int grp_base_aout, int grp_base_cc, int wg_tid,
                                         const float* __restrict__ gbu,
                                         const float* __restrict__ gba) {
    const int g = wg_tid >> 3, l8 = wg_tid & 7;
    float rsum = 0.f;
    #pragma unroll
    for (int w = 0; w < 8; ++w) rsum += redb[32 * 257 + w * 32 + g];
    float inv = __fdividef(1.0f, rsum + EPS);
    float plog = 0.f;
    #pragma unroll
    for (int t = 0; t < 2; ++t) {
        int p = 2 * l8 + t;
        float s1 = 0.f, s2 = 0.f;
        #pragma unroll
        for (int w = 0; w < 8; ++w) {
            s1 += redb[p * 257        + w * 32 + g];
            s2 += redb[(p + 16) * 257 + w * 32 + g];
        }
        float mu = s1 * inv;
        float sg = (s2 - 2.f * mu * s1 + mu * mu * rsum) * inv + EPS;
        sm[grp_base_nmu + g * 18 + p] = -mu;
        sm[grp_base_is  + g * 18 + p] = __fdividef(0.5f, sg);
        plog += __logf(sg);
    }
    #pragma unroll
    for (int d = 1; d < 8; d <<= 1) plog += __shfl_xor_sync(0xffffffffu, plog, d);
    if (l8 == 0) {
        float cost = rsum * (16.f * gbu[g] + 0.5f * plog);
        float ao = __fdividef(1.f, 1.f + __expf(LAM * (cost - gba[g])));
        sm[grp_base_aout + g] = ao;
        sm[grp_base_cc + g]   = __logf(ao) - 0.5f * plog - 8.f * LN2PI;
    }
}

__global__ void __launch_bounds__(NTHR, 1)
convcaps_kernel(const float* __restrict__ gx, const float* __restrict__ ga,
                const float* __restrict__ gbu, const float* __restrict__ gba,
                float* __restrict__ gout)
{
    extern __shared__ float sm[];
    const int tid    = threadIdx.x;
    const int grp    = tid >> 8;           // 0 or 1: position group
    const int wg_tid = tid & 255;
    const int warp8  = wg_tid >> 5;        // warp index within group (0..7)
    const int c      = tid & 31;

    const int pos = blockIdx.x * 2 + grp;  // 0..287
    const int b   = pos / 36;
    const int hw  = pos - b * 36;
    const int h2  = (hw / 6) * 2;
    const int w2  = (hw % 6) * 2;

    const int POSE_B = grp ? SM_POSE1 : SM_POSE0;
    const int ACT_B  = grp ? SM_ACT1  : SM_ACT0;
    const int NMU_B  = grp ? SM_NMU1  : SM_NMU0;
    const int IS_B   = grp ? SM_IS1   : SM_IS0;
    const int AOUT_B = grp ? SM_AOUT1 : SM_AOUT0;
    const int CC_B   = grp ? SM_CC1   : SM_CC0;
    float* redb = sm + (grp ? SM_REDG1 : SM_REDG0);

    // ---- load pose patch (dup-packed rows) + activations for this group ----
    for (int idx = wg_tid; idx < KKB * 16; idx += 256) {
        int n = idx >> 4, q = idx & 15;
        int ki = n / 96; int rem = n - ki * 96;
        int kj = rem >> 5; int bi = rem & 31;
        float f = gx[(size_t)((b * 14 + h2 + ki) * 14 + (w2 + kj)) * 512 + bi * 16 + q];
        *(float2*)(sm + POSE_B + n * 32 + 2 * q) = make_float2(f, f);
    }
    for (int n = wg_tid; n < KKB; n += 256) {
        int ki = n / 96; int rem = n - ki * 96;
        int kj = rem >> 5; int bi = rem & 31;
        sm[ACT_B + n] = ga[((b * 14 + h2 + ki) * 14 + (w2 + kj)) * 32 + bi];
    }
    __syncthreads();

    for (int pass = 0; pass < 3; ++pass) {
        u64 nmu2[8], is2[8];
        float ccst = 0.f;
        if (pass) {
            #pragma unroll
            for (int pp = 0; pp < 8; ++pp) {
                nmu2[pp] = *(const u64*)(sm + NMU_B + c * 18 + 2 * pp);
                is2[pp]  = *(const u64*)(sm + IS_B  + c * 18 + 2 * pp);
            }
            ccst = sm[CC_B + c];
        }
        u64 S1[8], S2[8];
        #pragma unroll
        for (int pp = 0; pp < 8; ++pp) { S1[pp] = 0ull; S2[pp] = 0ull; }
        float rs = 0.f;

        issue_chunk(sm, 0, tid);
        for (int j = 0; j < 18; ++j) {
            if (j < 17) { issue_chunk(sm, j + 1, tid); cp_wait1(); }
            else        { cp_wait0(); }
            __syncthreads();

            const int n0 = 16 * j + warp8;
            const int n1 = n0 + 8;
            const ulonglong2* Wb = (const ulonglong2*)(sm + ((j & 1) ? SM_STAGE1 : SM_STAGE0));
            u64 va[8], vb[8];
            compute_v2s(Wb + (warp8 * 128 + c),       sm + POSE_B + n0 * 32, va);
            compute_v2s(Wb + ((warp8 + 8) * 128 + c), sm + POSE_B + n1 * 32, vb);

            float r0, r1;
            if (pass == 0) {
                r0 = sm[ACT_B + n0] * (1.0f / 32.0f);
                r1 = sm[ACT_B + n1] * (1.0f / 32.0f);
            } else {
                float l0 = ccst - dist16(va, nmu2, is2);
                float l1 = ccst - dist16(vb, nmu2, is2);
                float m0 = redmax32f(l0);
                float m1 = redmax32f(l1);
                float e0 = __expf(l0 - m0);
                float e1 = __expf(l1 - m1);
                float s0 = e0, s1 = e1;
                wsum32x2(s0, s1);
                r0 = __fdividef(e0, s0);
                r1 = __fdividef(e1, s1);
            }
            rs += r0 + r1;
            macc2(r0, va, S1, S2);
            macc2(r1, vb, S1, S2);
            __syncthreads();   // buffer (j&1) reused by chunk j+2's issue next iter
        }

        store_red(redb, warp8, c, S1, S2, rs);
        __syncthreads();
        finalize(sm, redb, NMU_B, IS_B, AOUT_B, CC_B, wg_tid, gbu, gba);
        __syncthreads();
    }

    // ---- outputs: p_out (pos*512) then a_out (147456 + pos*32) ----
    for (int idx = wg_tid; idx < 512; idx += 256) {
        int co = idx >> 4, p = idx & 15;
        gout[(size_t)pos * 512 + idx] = -sm[NMU_B + co * 18 + p];
    }
    if (wg_tid < 32)
        gout[147456 + pos * 32 + wg_tid] = sm[AOUT_B + wg_tid];
}

extern "C" void kernel_launch(void* const* d_in, const int* in_sizes, int n_in,
                              void* d_out, int out_size) {
    const float* x  = (const float*)d_in[0];
    const float* a  = (const float*)d_in[1];
    const float* w  = (const float*)d_in[2];
    const float* bu = (const float*)d_in[3];
    const float* ba = (const float*)d_in[4];
    float* out = (float*)d_out;
    (void)in_sizes; (void)n_in; (void)out_size;

    transpose_w_kernel<<<576, 256>>>(w);

    const int smem_bytes = SM_TOTAL * (int)sizeof(float);  // 153616 B
    cudaFuncSetAttribute(convcaps_kernel,
                         cudaFuncAttributeMaxDynamicSharedMemorySize, smem_bytes);
    convcaps_kernel<<<144, NTHR, smem_bytes>>>(x, a, bu, ba, out);
}